// round 14
// baseline (speedup 1.0000x reference)
#include <cuda_runtime.h>
#include <cuda_fp16.h>

#define EMB   512
#define BATCH 256
#define NCLS  6
#define NCTA  128
#define NGRP  32          // CTAs per independent b-group
#define NTHR  256
#define TMAX  512
#define CONV_EPS 1.5e-3f

#define BPITCH 1040   // bytes/row of w in smem (padded)
#define WS_PL  49920  // one w plane: 48 * 1040
#define HS_OFF 99840
#define HS_PL  32768  // one h plane chunk (256 k): 64 rows * 512B, XOR-swizzled
#define HS_BUF 65536  // 2 planes
#define SMEM_BYTES (HS_OFF + 2 * HS_BUF)   // 230912

typedef unsigned int u32;
typedef unsigned long long u64;
typedef unsigned short us16;

// ---- persistent device state ----
__device__ us16 g_xp[2][BATCH * EMB];        // x fp16 hi/lo planes
__device__ us16 g_hp[2][2][BATCH * EMB];     // h[step parity][plane]
// flag-relay barrier state: one 128B line of 32 tagged-mx slots per (group, parity)
__device__ __align__(128) volatile int g_flag[4][2][32];
__device__ volatile unsigned g_rel[4 * 32]; // release word per group (128B padded)
// prelude barrier (sense-reversing, replay-safe)
__device__ unsigned g_cnt4[4 * 32];
__device__ volatile unsigned g_gen4[4 * 32];

__device__ __forceinline__ u32 smem_u32(const void* p) {
    u32 a; asm("{ .reg .u64 t; cvta.to.shared.u64 t, %1; cvt.u32.u64 %0, t; }" : "=r"(a) : "l"(p));
    return a;
}
__device__ __forceinline__ void cp16(u32 dst, const void* src) {
    u64 g = (u64)__cvta_generic_to_global(src);
    asm volatile("cp.async.cg.shared.global [%0], [%1], 16;" :: "r"(dst), "l"(g));
}
__device__ __forceinline__ void ldsm_x4(u32& r0, u32& r1, u32& r2, u32& r3, u32 addr) {
    asm volatile("ldmatrix.sync.aligned.m8n8.x4.shared.b16 {%0,%1,%2,%3}, [%4];"
                 : "=r"(r0), "=r"(r1), "=r"(r2), "=r"(r3) : "r"(addr));
}
__device__ __forceinline__ void ldsm_x2(u32& r0, u32& r1, u32 addr) {
    asm volatile("ldmatrix.sync.aligned.m8n8.x2.shared.b16 {%0,%1}, [%2];"
                 : "=r"(r0), "=r"(r1) : "r"(addr));
}
__device__ __forceinline__ void mma16816(float* d, u32 a0, u32 a1, u32 a2, u32 a3,
                                         u32 b0, u32 b1) {
    asm volatile("mma.sync.aligned.m16n8k16.row.col.f32.f16.f16.f32 "
                 "{%0,%1,%2,%3}, {%4,%5,%6,%7}, {%8,%9}, {%0,%1,%2,%3};"
                 : "+f"(d[0]), "+f"(d[1]), "+f"(d[2]), "+f"(d[3])
                 : "r"(a0), "r"(a1), "r"(a2), "r"(a3), "r"(b0), "r"(b1));
}
__device__ __forceinline__ float sigm(float v) { return 1.f / (1.f + __expf(-v)); }

// ---- prelude barrier (used before the recurrent loop) ----
__device__ __forceinline__ void groupbar(int bt) {
    __syncthreads();
    __threadfence();
    if (threadIdx.x == 0) {
        unsigned* cnt = &g_cnt4[bt * 32];
        volatile unsigned* gen = &g_gen4[bt * 32];
        unsigned my = *gen;
        unsigned a = atomicAdd(cnt, 1u);
        if (a == NGRP - 1u) {
            *cnt = 0;
            __threadfence();
            *gen = my + 1u;
        } else {
            while (*gen == my) { }
        }
    }
    __syncthreads();
    __threadfence();
}

// ---- stage one 256-k chunk (both fp16 planes, 64 rows) via cp.async ----
__device__ __forceinline__ void stage_chunk(u32 dst, const us16* hi, const us16* lo,
                                            int B0, int kc, int tid) {
    #pragma unroll
    for (int i = 0; i < 16; i++) {
        int idx = tid + i * NTHR;          // 0..4095
        int pl  = idx >> 11;
        int rem = idx & 2047;
        int row = rem >> 5;                // 0..63
        int u   = rem & 31;                // 16B unit along k
        const us16* src = (pl ? lo : hi) + (size_t)(B0 + row) * EMB + kc + u * 8;
        cp16(dst + pl * HS_PL + row * 512 + ((u ^ (row & 7)) << 4), src);
    }
    asm volatile("cp.async.commit_group;" ::: "memory");
}

// ---- full K=512 pass ----
// acc[3][4]  = h_hi@w_hi + h_lo@w_hi   (every step)
// cwl[3][4]  = h_hi@w_lo               (recomputed only when REFRESH)
// Caller pre-stages chunk0 into buf0.
template<bool REFRESH>
__device__ __forceinline__ void mma_pass(u32 smb, const us16* hi, const us16* lo, int B0,
                                         float acc[3][4], float cwl[3][4],
                                         u32 a_base, u32 arx, u32 ahi,
                                         u32 b4_off, u32 b2_off, int tid) {
    #pragma unroll
    for (int g = 0; g < 3; g++)
        #pragma unroll
        for (int q = 0; q < 4; q++) {
            acc[g][q] = 0.f;
            if (REFRESH) cwl[g][q] = 0.f;
        }

    #pragma unroll
    for (int c = 0; c < 2; c++) {
        if (c == 0) {
            stage_chunk(smb + HS_OFF + HS_BUF, hi, lo, B0, 256, tid);
            asm volatile("cp.async.wait_group 1;" ::: "memory");
        } else {
            asm volatile("cp.async.wait_group 0;" ::: "memory");
        }
        __syncthreads();

        u32 ab = smb + HS_OFF + c * HS_BUF + a_base;
        #pragma unroll
        for (int kk = 0; kk < 16; kk++) {
            u32 au = (u32)(((kk * 2 + ahi) ^ arx) << 4);
            u32 kb = (u32)(c * 512 + kk * 32);
            u32 ah0, ah1, ah2, ah3, al0, al1, al2, al3;
            u32 bh0, bh1, bh2, bh3, bg0, bg1;
            ldsm_x4(ah0, ah1, ah2, ah3, ab + au);
            ldsm_x4(al0, al1, al2, al3, ab + HS_PL + au);
            ldsm_x4(bh0, bh1, bh2, bh3, smb + b4_off + kb);
            ldsm_x2(bg0, bg1,           smb + b2_off + kb);
            // main + h_lo correction (every step)
            mma16816(acc[0], ah0, ah1, ah2, ah3, bh0, bh1);
            mma16816(acc[1], ah0, ah1, ah2, ah3, bh2, bh3);
            mma16816(acc[2], ah0, ah1, ah2, ah3, bg0, bg1);
            mma16816(acc[0], al0, al1, al2, al3, bh0, bh1);
            mma16816(acc[1], al0, al1, al2, al3, bh2, bh3);
            mma16816(acc[2], al0, al1, al2, al3, bg0, bg1);
            if (REFRESH) {
                u32 cl0, cl1, cl2, cl3, cg0, cg1;
                ldsm_x4(cl0, cl1, cl2, cl3, smb + WS_PL + b4_off + kb);
                ldsm_x2(cg0, cg1,           smb + WS_PL + b2_off + kb);
                mma16816(cwl[0], ah0, ah1, ah2, ah3, cl0, cl1);
                mma16816(cwl[1], ah0, ah1, ah2, ah3, cl2, cl3);
                mma16816(cwl[2], ah0, ah1, ah2, ah3, cg0, cg1);
            }
        }
    }
}

// ---- load a 48-row weight slice into fp16 hi/lo smem planes (padded pitch) ----
__device__ __forceinline__ void load_ws(char* smraw, const float* wsrc, int J0, int tid) {
    us16* whi = (us16*)smraw;
    us16* wlo = (us16*)(smraw + WS_PL);
    for (int e = tid; e < 48 * EMB; e += NTHR) {
        int n = e >> 9, k = e & 511;
        int g = n >> 4, jj = n & 15;
        float w = wsrc[((size_t)(g * EMB + J0 + jj)) * EMB + k];
        __half h = __float2half_rn(w);
        __half l = __float2half_rn(w - __half2float(h));
        whi[n * (BPITCH / 2) + k] = *(us16*)&h;
        wlo[n * (BPITCH / 2) + k] = *(us16*)&l;
    }
}

__global__ void __launch_bounds__(NTHR, 1)
gru_mma_kernel(const float* __restrict__ c,     const float* __restrict__ fc_w,
               const float* __restrict__ fc_b,  const float* __restrict__ w_ih,
               const float* __restrict__ b_ih,  const float* __restrict__ w_hh,
               const float* __restrict__ b_hh,  const float* __restrict__ head_w,
               const float* __restrict__ head_b,const int*   __restrict__ maxT,
               float* __restrict__ out)
{
    extern __shared__ char smraw[];
    const u32 smb = smem_u32(smraw);
    __shared__ int s_wmax[8];
    __shared__ int s_conv;

    const int tid = threadIdx.x;
    const int cta = blockIdx.x;
    const int wid = tid >> 5, lane = tid & 31;

    int T = (maxT != nullptr) ? maxT[0] : TMAX;
    if (T < 1 || T > TMAX) T = TMAX;

    const int bt = cta >> 5;                 // b-group 0..3 (independent)
    const int jt = cta & 31;                 // j-tile within group
    const int B0 = bt * 64;
    const int J0 = jt * 16;
    const int lg = jt * NTHR + tid;          // 0..8191 within group
    const int mtile = wid & 3, p = wid >> 2;

    // A fragment per-lane constants (swizzled layout)
    const int arow = mtile * 16 + (lane & 15);          // 0..63
    const u32 a_base = (u32)(arow * 512);
    const u32 arx    = (u32)(arow & 7);
    const u32 ahi    = (u32)(lane >> 4);                // 0/1

    // B fragment per-lane byte offsets (padded layout)
    const u32 b4_off = (u32)(((lane >> 4) * 16 + p * 8 + (lane & 7)) * BPITCH
                             + ((lane >> 3) & 1) * 16);
    const u32 b2_off = (u32)((32 + p * 8 + (lane & 7)) * BPITCH + ((lane >> 3) & 1) * 16);

    // this thread's 4 output cells: rows r0,r0+8 ; cols j0,j0+1
    const int r0 = B0 + mtile * 16 + (lane >> 2);
    const int j0 = J0 + p * 8 + 2 * (lane & 3);

    const int group16 = tid >> 4, lane16 = tid & 15;
    // head assignment (group-local): 384 dots over 32 CTAs
    const int hp_idx = jt * 12 + group16;               // 0..383 (group16<12)
    const int hb = B0 + hp_idx / NCLS, hk = hp_idx % NCLS;

    // ---------------- Phase A (group-local): init + x = tanh(c @ fc_w^T + fc_b) ----
    for (int i = lg; i < 64 * EMB; i += NGRP * NTHR) {
        int o = B0 * EMB + i;
        g_hp[0][0][o] = 0; g_hp[0][1][o] = 0;
    }
    // reset flag-relay state for this launch (replay-safe)
    for (int i = lg; i < 64; i += NGRP * NTHR)
        g_flag[bt][i >> 5][i & 31] = 1;   // LSB=1 != first tag(0)
    if (lg == 0) g_rel[bt * 32] = 0;

    for (int i = lg; i < 64 * EMB; i += NGRP * NTHR) {
        int o = B0 * EMB + i;
        int b = o >> 9, ii = o & 511;
        const float4* cr = (const float4*)(c + (size_t)b * EMB);
        const float4* wr = (const float4*)(fc_w + (size_t)ii * EMB);
        float s = 0.f;
        #pragma unroll 8
        for (int k = 0; k < EMB / 4; k++) {
            float4 a = cr[k], wv = wr[k];
            s += a.x * wv.x + a.y * wv.y + a.z * wv.z + a.w * wv.w;
        }
        float x = tanhf(s + fc_b[ii]);
        __half xh = __float2half_rn(x);
        __half xl = __float2half_rn(x - __half2float(xh));
        g_xp[0][o] = *(us16*)&xh; g_xp[1][o] = *(us16*)&xl;
    }
    groupbar(bt);

    // ---------------- gi pass: ws <- w_ih ; acc+cwl = x @ w_ih^T (3 products) ------
    load_ws(smraw, w_ih, J0, tid);
    __syncthreads();

    float acc[3][4], cwl[3][4];
    stage_chunk(smb + HS_OFF, g_xp[0], g_xp[1], B0, 0, tid);
    mma_pass<true>(smb, g_xp[0], g_xp[1], B0, acc, cwl,
                   a_base, arx, ahi, b4_off, b2_off, tid);

    float gir[4], giz[4], gin[4], bhn[4], hprev[4];
    #pragma unroll
    for (int q = 0; q < 4; q++) {
        int jq = j0 + (q & 1);
        gir[q] = acc[0][q] + cwl[0][q] + b_ih[jq]           + b_hh[jq];
        giz[q] = acc[1][q] + cwl[1][q] + b_ih[EMB + jq]     + b_hh[EMB + jq];
        gin[q] = acc[2][q] + cwl[2][q] + b_ih[2 * EMB + jq];
        bhn[q] = b_hh[2 * EMB + jq];
        hprev[q] = 0.f;
    }
    __syncthreads();

    // ---------------- ws <- w_hh (resident for the whole recurrence) ---------------
    load_ws(smraw, w_hh, J0, tid);
    __syncthreads();
    groupbar(bt);   // ensure every CTA's flag/rel resets are globally visible

    const float* hw = head_w + (size_t)hk * EMB;
    const unsigned shm = 0xFFFFu << (tid & 16);

    // ---------------- Recurrent loop -----------------------------------------------
    for (int t = 0; t < T; t++) {
        const us16* chi = g_hp[t & 1][0];
        const us16* clo = g_hp[t & 1][1];
        us16* nhi = g_hp[(t + 1) & 1][0];
        us16* nlo = g_hp[(t + 1) & 1][1];

        // kick off chunk 0 of h_t staging, then do the deferred head(t-1) in its shadow
        stage_chunk(smb + HS_OFF, chi, clo, B0, 0, tid);

        if (t > 0 && group16 < 12) {
            // head for step t-1 reads h_t (= chi/clo) — same lines being staged
            const us16* phi = chi + (size_t)hb * EMB;
            const us16* plo = clo + (size_t)hb * EMB;
            float s = 0.f;
            #pragma unroll 8
            for (int jj = lane16; jj < EMB; jj += 16) {
                us16 uh = __ldcg(&phi[jj]), ul = __ldcg(&plo[jj]);
                s += (__half2float(*(__half*)&uh) + __half2float(*(__half*)&ul)) * hw[jj];
            }
            s += __shfl_down_sync(shm, s, 8, 16);
            s += __shfl_down_sync(shm, s, 4, 16);
            s += __shfl_down_sync(shm, s, 2, 16);
            s += __shfl_down_sync(shm, s, 1, 16);
            if (lane16 == 0)
                out[(size_t)hb * T * NCLS + (size_t)(t - 1) * NCLS + hk] = s + head_b[hk];
        }

        // refresh the quasi-static h@w_lo correction every 4th step
        if ((t & 3) == 0)
            mma_pass<true >(smb, chi, clo, B0, acc, cwl,
                            a_base, arx, ahi, b4_off, b2_off, tid);
        else
            mma_pass<false>(smb, chi, clo, B0, acc, cwl,
                            a_base, arx, ahi, b4_off, b2_off, tid);

        float mx = 0.f;
        u32 packh[2], packl[2];
        #pragma unroll
        for (int q = 0; q < 4; q++) {
            float r = sigm(gir[q] + acc[0][q] + cwl[0][q]);
            float z = sigm(giz[q] + acc[1][q] + cwl[1][q]);
            float n = tanhf(gin[q] + r * (acc[2][q] + cwl[2][q] + bhn[q]));
            float hnew = (1.f - z) * n + z * hprev[q];
            mx = fmaxf(mx, fabsf(hnew - hprev[q]));
            hprev[q] = hnew;
            __half hh = __float2half_rn(hnew);
            __half hl = __float2half_rn(hnew - __half2float(hh));
            int half = q >> 1, slot = q & 1;
            ((us16*)&packh[half])[slot] = *(us16*)&hh;
            ((us16*)&packl[half])[slot] = *(us16*)&hl;
        }
        size_t o0 = (size_t)r0 * EMB + j0, o1 = (size_t)(r0 + 8) * EMB + j0;
        __stcg((u32*)(nhi + o0), packh[0]);
        __stcg((u32*)(nhi + o1), packh[1]);
        __stcg((u32*)(nlo + o0), packl[0]);
        __stcg((u32*)(nlo + o1), packl[1]);

        // ---- flag-relay barrier: arrival + conv-reduce + release in one round ----
        const int tag = (t >> 1) & 1;
        int wmax = __reduce_max_sync(0xFFFFFFFFu, __float_as_int(mx));
        if (lane == 0) s_wmax[wid] = wmax;
        __threadfence();       // h stores globally visible before flag
        __syncthreads();       // all threads' stores + s_wmax complete
        if (tid == 0) {
            int m = s_wmax[0];
            #pragma unroll
            for (int i = 1; i < 8; i++) m = max(m, s_wmax[i]);
            g_flag[bt][t & 1][jt] = (m & ~1) | tag;
        }
        if (jt == 0 && tid == 0) {
            // master: wait for all 32 flags (one 128B line), reduce, publish
            volatile int* vf = &g_flag[bt][t & 1][0];
            for (;;) {
                bool ok = true;
                #pragma unroll 4
                for (int i = 0; i < 32; i++)
                    if ((vf[i] & 1) != tag) { ok = false; break; }
                if (ok) break;
            }
            int gm = 0;
            #pragma unroll 4
            for (int i = 0; i < 32; i++) gm = max(gm, vf[i] & ~1);
            int cv = (__int_as_float(gm) < CONV_EPS) ? 1 : 0;
            __threadfence();
            g_rel[bt * 32] = (unsigned)(((t + 1) << 1) | cv);
        }
        if (tid == 0) {
            unsigned gw;
            while ((int)((gw = g_rel[bt * 32]) >> 1) <= t) { }
            s_conv = (int)(gw & 1u);
        }
        __syncthreads();
        const bool conv = (s_conv != 0);
        __threadfence();       // acquire: h_{t+1} from all CTAs now readable

        if (conv || t == T - 1) {
            // tail head for step t (+ fixed-point broadcast if converged)
            if (group16 < 12) {
                const us16* phi = nhi + (size_t)hb * EMB;
                const us16* plo = nlo + (size_t)hb * EMB;
                float s = 0.f;
                #pragma unroll 8
                for (int jj = lane16; jj < EMB; jj += 16) {
                    us16 uh = __ldcg(&phi[jj]), ul = __ldcg(&plo[jj]);
                    s += (__half2float(*(__half*)&uh) + __half2float(*(__half*)&ul)) * hw[jj];
                }
                s += __shfl_down_sync(shm, s, 8, 16);
                s += __shfl_down_sync(shm, s, 4, 16);
                s += __shfl_down_sync(shm, s, 2, 16);
                s += __shfl_down_sync(shm, s, 1, 16);
                if (lane16 == 0) {
                    float val = s + head_b[hk];
                    size_t base = (size_t)hb * T * NCLS + (size_t)hk;
                    out[base + (size_t)t * NCLS] = val;
                    for (int tt = t + 1; tt < T; tt++)
                        out[base + (size_t)tt * NCLS] = val;
                }
            }
            break;
        }
    }
}

extern "C" void kernel_launch(void* const* d_in, const int* in_sizes, int n_in,
                              void* d_out, int out_size)
{
    (void)in_sizes; (void)out_size;
    const float* c      = (const float*)d_in[0];
    const float* fc_w   = (const float*)d_in[1];
    const float* fc_b   = (const float*)d_in[2];
    const float* w_ih   = (const float*)d_in[3];
    const float* b_ih   = (const float*)d_in[4];
    const float* w_hh   = (const float*)d_in[5];
    const float* b_hh   = (const float*)d_in[6];
    const float* head_w = (const float*)d_in[7];
    const float* head_b = (const float*)d_in[8];
    const int*   maxT   = (n_in > 9) ? (const int*)d_in[9] : nullptr;

    cudaFuncSetAttribute(gru_mma_kernel,
                         cudaFuncAttributeMaxDynamicSharedMemorySize, SMEM_BYTES);
    gru_mma_kernel<<<NCTA, NTHR, SMEM_BYTES>>>(c, fc_w, fc_b, w_ih, b_ih, w_hh, b_hh,
                                               head_w, head_b, maxT, (float*)d_out);
}

// round 16
// speedup vs baseline: 2.0741x; 2.0741x over previous
#include <cuda_runtime.h>
#include <cuda_fp16.h>

#define EMB   512
#define BATCH 256
#define NCLS  6
#define NCTA  128
#define NGRP  32          // CTAs per independent b-group
#define NTHR  256
#define TMAX  512
#define CONV_EPS 1.5e-3f

#define BPITCH 1040   // bytes/row of w in smem (padded)
#define WS_PL  49920  // one w plane: 48 * 1040
#define HS_OFF 99840
#define HS_PL  32768  // one h plane chunk (256 k): 64 rows * 512B, XOR-swizzled
#define HS_BUF 65536  // 2 planes
#define SMEM_BYTES (HS_OFF + 2 * HS_BUF)   // 230912

typedef unsigned int u32;
typedef unsigned long long u64;
typedef unsigned short us16;

// ---- persistent device state ----
__device__ us16 g_xp[2][BATCH * EMB];        // x fp16 hi/lo planes
__device__ us16 g_hp[2][2][BATCH * EMB];     // h[step parity][plane]
__device__ int  g_md4[4][TMAX];
__device__ unsigned g_cnt4[4 * 32];          // 128B-padded per group
__device__ volatile unsigned g_gen4[4 * 32];

__device__ __forceinline__ u32 smem_u32(const void* p) {
    u32 a; asm("{ .reg .u64 t; cvta.to.shared.u64 t, %1; cvt.u32.u64 %0, t; }" : "=r"(a) : "l"(p));
    return a;
}
__device__ __forceinline__ void cp16(u32 dst, const void* src) {
    u64 g = (u64)__cvta_generic_to_global(src);
    asm volatile("cp.async.cg.shared.global [%0], [%1], 16;" :: "r"(dst), "l"(g));
}
__device__ __forceinline__ void ldsm_x4(u32& r0, u32& r1, u32& r2, u32& r3, u32 addr) {
    asm volatile("ldmatrix.sync.aligned.m8n8.x4.shared.b16 {%0,%1,%2,%3}, [%4];"
                 : "=r"(r0), "=r"(r1), "=r"(r2), "=r"(r3) : "r"(addr));
}
__device__ __forceinline__ void ldsm_x2(u32& r0, u32& r1, u32 addr) {
    asm volatile("ldmatrix.sync.aligned.m8n8.x2.shared.b16 {%0,%1}, [%2];"
                 : "=r"(r0), "=r"(r1) : "r"(addr));
}
__device__ __forceinline__ void mma16816(float* d, u32 a0, u32 a1, u32 a2, u32 a3,
                                         u32 b0, u32 b1) {
    asm volatile("mma.sync.aligned.m16n8k16.row.col.f32.f16.f16.f32 "
                 "{%0,%1,%2,%3}, {%4,%5,%6,%7}, {%8,%9}, {%0,%1,%2,%3};"
                 : "+f"(d[0]), "+f"(d[1]), "+f"(d[2]), "+f"(d[3])
                 : "r"(a0), "r"(a1), "r"(a2), "r"(a3), "r"(b0), "r"(b1));
}
__device__ __forceinline__ float sigm(float v) { return 1.f / (1.f + __expf(-v)); }

// ---- per-group (32-CTA) sense-reversing barrier (proven R12 version) ----
__device__ __forceinline__ void groupbar(int bt) {
    __syncthreads();
    __threadfence();
    if (threadIdx.x == 0) {
        unsigned* cnt = &g_cnt4[bt * 32];
        volatile unsigned* gen = &g_gen4[bt * 32];
        unsigned my = *gen;
        unsigned a = atomicAdd(cnt, 1u);
        if (a == NGRP - 1u) {
            *cnt = 0;
            __threadfence();
            *gen = my + 1u;
        } else {
            while (*gen == my) { }
        }
    }
    __syncthreads();
    __threadfence();
}

// ---- stage one 256-k chunk (both fp16 planes, 64 rows) via cp.async ----
__device__ __forceinline__ void stage_chunk(u32 dst, const us16* hi, const us16* lo,
                                            int B0, int kc, int tid) {
    #pragma unroll
    for (int i = 0; i < 16; i++) {
        int idx = tid + i * NTHR;          // 0..4095
        int pl  = idx >> 11;
        int rem = idx & 2047;
        int row = rem >> 5;                // 0..63
        int u   = rem & 31;                // 16B unit along k
        const us16* src = (pl ? lo : hi) + (size_t)(B0 + row) * EMB + kc + u * 8;
        cp16(dst + pl * HS_PL + row * 512 + ((u ^ (row & 7)) << 4), src);
    }
    asm volatile("cp.async.commit_group;" ::: "memory");
}

// ---- full K=512 pass ----
// acc[3][4]  = h_hi@w_hi + h_lo@w_hi   (every step)
// cwl[3][4]  = h_hi@w_lo               (recomputed only when REFRESH)
// Caller pre-stages chunk0 into buf0.
template<bool REFRESH>
__device__ __forceinline__ void mma_pass(u32 smb, const us16* hi, const us16* lo, int B0,
                                         float acc[3][4], float cwl[3][4],
                                         u32 a_base, u32 arx, u32 ahi,
                                         u32 b4_off, u32 b2_off, int tid) {
    #pragma unroll
    for (int g = 0; g < 3; g++)
        #pragma unroll
        for (int q = 0; q < 4; q++) {
            acc[g][q] = 0.f;
            if (REFRESH) cwl[g][q] = 0.f;
        }

    #pragma unroll
    for (int c = 0; c < 2; c++) {
        if (c == 0) {
            stage_chunk(smb + HS_OFF + HS_BUF, hi, lo, B0, 256, tid);
            asm volatile("cp.async.wait_group 1;" ::: "memory");
        } else {
            asm volatile("cp.async.wait_group 0;" ::: "memory");
        }
        __syncthreads();

        u32 ab = smb + HS_OFF + c * HS_BUF + a_base;
        #pragma unroll
        for (int kk = 0; kk < 16; kk++) {
            u32 au = (u32)(((kk * 2 + ahi) ^ arx) << 4);
            u32 kb = (u32)(c * 512 + kk * 32);
            u32 ah0, ah1, ah2, ah3, al0, al1, al2, al3;
            u32 bh0, bh1, bh2, bh3, bg0, bg1;
            ldsm_x4(ah0, ah1, ah2, ah3, ab + au);
            ldsm_x4(al0, al1, al2, al3, ab + HS_PL + au);
            ldsm_x4(bh0, bh1, bh2, bh3, smb + b4_off + kb);
            ldsm_x2(bg0, bg1,           smb + b2_off + kb);
            // main + h_lo correction (every step)
            mma16816(acc[0], ah0, ah1, ah2, ah3, bh0, bh1);
            mma16816(acc[1], ah0, ah1, ah2, ah3, bh2, bh3);
            mma16816(acc[2], ah0, ah1, ah2, ah3, bg0, bg1);
            mma16816(acc[0], al0, al1, al2, al3, bh0, bh1);
            mma16816(acc[1], al0, al1, al2, al3, bh2, bh3);
            mma16816(acc[2], al0, al1, al2, al3, bg0, bg1);
            if (REFRESH) {
                u32 cl0, cl1, cl2, cl3, cg0, cg1;
                ldsm_x4(cl0, cl1, cl2, cl3, smb + WS_PL + b4_off + kb);
                ldsm_x2(cg0, cg1,           smb + WS_PL + b2_off + kb);
                mma16816(cwl[0], ah0, ah1, ah2, ah3, cl0, cl1);
                mma16816(cwl[1], ah0, ah1, ah2, ah3, cl2, cl3);
                mma16816(cwl[2], ah0, ah1, ah2, ah3, cg0, cg1);
            }
        }
    }
}

// ---- load a 48-row weight slice into fp16 hi/lo smem planes (padded pitch) ----
__device__ __forceinline__ void load_ws(char* smraw, const float* wsrc, int J0, int tid) {
    us16* whi = (us16*)smraw;
    us16* wlo = (us16*)(smraw + WS_PL);
    for (int e = tid; e < 48 * EMB; e += NTHR) {
        int n = e >> 9, k = e & 511;
        int g = n >> 4, jj = n & 15;
        float w = wsrc[((size_t)(g * EMB + J0 + jj)) * EMB + k];
        __half h = __float2half_rn(w);
        __half l = __float2half_rn(w - __half2float(h));
        whi[n * (BPITCH / 2) + k] = *(us16*)&h;
        wlo[n * (BPITCH / 2) + k] = *(us16*)&l;
    }
}

__global__ void __launch_bounds__(NTHR, 1)
gru_mma_kernel(const float* __restrict__ c,     const float* __restrict__ fc_w,
               const float* __restrict__ fc_b,  const float* __restrict__ w_ih,
               const float* __restrict__ b_ih,  const float* __restrict__ w_hh,
               const float* __restrict__ b_hh,  const float* __restrict__ head_w,
               const float* __restrict__ head_b,const int*   __restrict__ maxT,
               float* __restrict__ out)
{
    extern __shared__ char smraw[];
    const u32 smb = smem_u32(smraw);
    __shared__ int s_mx;

    const int tid = threadIdx.x;
    const int cta = blockIdx.x;
    const int wid = tid >> 5, lane = tid & 31;

    int T = (maxT != nullptr) ? maxT[0] : TMAX;
    if (T < 1 || T > TMAX) T = TMAX;

    const int bt = cta >> 5;                 // b-group 0..3 (independent)
    const int jt = cta & 31;                 // j-tile within group
    const int B0 = bt * 64;
    const int J0 = jt * 16;
    const int lg = jt * NTHR + tid;          // 0..8191 within group
    const int mtile = wid & 3, p = wid >> 2;

    // A fragment per-lane constants (swizzled layout)
    const int arow = mtile * 16 + (lane & 15);          // 0..63
    const u32 a_base = (u32)(arow * 512);
    const u32 arx    = (u32)(arow & 7);
    const u32 ahi    = (u32)(lane >> 4);                // 0/1

    // B fragment per-lane byte offsets (padded layout)
    const u32 b4_off = (u32)(((lane >> 4) * 16 + p * 8 + (lane & 7)) * BPITCH
                             + ((lane >> 3) & 1) * 16);
    const u32 b2_off = (u32)((32 + p * 8 + (lane & 7)) * BPITCH + ((lane >> 3) & 1) * 16);

    // this thread's 4 output cells: rows r0,r0+8 ; cols j0,j0+1
    const int r0 = B0 + mtile * 16 + (lane >> 2);
    const int j0 = J0 + p * 8 + 2 * (lane & 3);

    const int group16 = tid >> 4, lane16 = tid & 15;
    // head assignment (group-local): 384 dots over 32 CTAs
    const int hp_idx = jt * 12 + group16;               // 0..383 (group16<12)
    const int hb = B0 + hp_idx / NCLS, hk = hp_idx % NCLS;

    // ---------------- Phase A (tiled in smem): x = tanh(c @ fc_w^T + fc_b) --------
    // This CTA computes x[B0:B0+64, J0:J0+16].
    for (int i = lg; i < 64 * EMB; i += NGRP * NTHR) {
        int o = B0 * EMB + i;
        g_hp[0][0][o] = 0; g_hp[0][1][o] = 0;
    }
    for (int i = lg; i < TMAX; i += NGRP * NTHR) ((volatile int*)g_md4[bt])[i] = 0;

    {
        float* wfs = (float*)smraw;                   // 16 rows x 513 floats (32.8KB)
        float* cfs = (float*)(smraw + HS_OFF);        // 64 rows x 512 floats (128KB)

        // stage fc_w rows J0..J0+15 (fp32) into smem, pitch 513 (bank-spread)
        for (int e = tid; e < 16 * 128; e += NTHR) {
            int r = e >> 7, kq = (e & 127) << 2;
            float4 v = *(const float4*)(fc_w + (size_t)(J0 + r) * EMB + kq);
            float* dst = wfs + r * 513 + kq;
            dst[0] = v.x; dst[1] = v.y; dst[2] = v.z; dst[3] = v.w;
        }
        // stage c rows B0..B0+63 (fp32) via cp.async
        for (int e = tid; e < 64 * 128; e += NTHR) {
            int r = e >> 7, kq = (e & 127) << 2;
            cp16(smb + HS_OFF + (u32)((r * 512 + kq) << 2),
                 c + (size_t)(B0 + r) * EMB + kq);
        }
        asm volatile("cp.async.commit_group;" ::: "memory");
        asm volatile("cp.async.wait_group 0;" ::: "memory");
        __syncthreads();

        // compute 4 outputs: i = J0+il, b = B0+b4 .. +3
        const int il = tid & 15, b4 = (tid >> 4) << 2;
        const float* wrow = wfs + il * 513;
        const float* c0 = cfs + b4 * 512;
        float ax0 = 0.f, ax1 = 0.f, ax2 = 0.f, ax3 = 0.f;
        #pragma unroll 8
        for (int k = 0; k < 512; k++) {
            float wv = wrow[k];
            ax0 += c0[k] * wv;
            ax1 += c0[512 + k] * wv;
            ax2 += c0[1024 + k] * wv;
            ax3 += c0[1536 + k] * wv;
        }
        float bb = fc_b[J0 + il];
        float xs[4] = { tanhf(ax0 + bb), tanhf(ax1 + bb), tanhf(ax2 + bb), tanhf(ax3 + bb) };
        #pragma unroll
        for (int q = 0; q < 4; q++) {
            size_t o = (size_t)(B0 + b4 + q) * EMB + (J0 + il);
            __half xh = __float2half_rn(xs[q]);
            __half xl = __float2half_rn(xs[q] - __half2float(xh));
            g_xp[0][o] = *(us16*)&xh; g_xp[1][o] = *(us16*)&xl;
        }
        __syncthreads();   // smem reuse safe before load_ws/stage
    }
    groupbar(bt);

    // ---------------- gi pass: ws <- w_ih ; acc+cwl = x @ w_ih^T (3 products) ------
    load_ws(smraw, w_ih, J0, tid);
    __syncthreads();

    float acc[3][4], cwl[3][4];
    stage_chunk(smb + HS_OFF, g_xp[0], g_xp[1], B0, 0, tid);
    mma_pass<true>(smb, g_xp[0], g_xp[1], B0, acc, cwl,
                   a_base, arx, ahi, b4_off, b2_off, tid);

    float gir[4], giz[4], gin[4], bhn[4], hprev[4];
    #pragma unroll
    for (int q = 0; q < 4; q++) {
        int jq = j0 + (q & 1);
        gir[q] = acc[0][q] + cwl[0][q] + b_ih[jq]           + b_hh[jq];
        giz[q] = acc[1][q] + cwl[1][q] + b_ih[EMB + jq]     + b_hh[EMB + jq];
        gin[q] = acc[2][q] + cwl[2][q] + b_ih[2 * EMB + jq];
        bhn[q] = b_hh[2 * EMB + jq];
        hprev[q] = 0.f;
    }
    __syncthreads();

    // ---------------- ws <- w_hh (resident for the whole recurrence) ---------------
    load_ws(smraw, w_hh, J0, tid);
    __syncthreads();

    const float* hw = head_w + (size_t)hk * EMB;
    const unsigned shm = 0xFFFFu << (tid & 16);

    // ---------------- Recurrent loop -----------------------------------------------
    for (int t = 0; t < T; t++) {
        const us16* chi = g_hp[t & 1][0];
        const us16* clo = g_hp[t & 1][1];
        us16* nhi = g_hp[(t + 1) & 1][0];
        us16* nlo = g_hp[(t + 1) & 1][1];

        if (tid == 0) s_mx = 0;
        // kick off chunk 0 of h_t staging, then do the deferred head(t-1) in its shadow
        stage_chunk(smb + HS_OFF, chi, clo, B0, 0, tid);

        if (t > 0 && group16 < 12) {
            // head for step t-1 reads h_t (= chi/clo) — same lines being staged
            const us16* phi = chi + (size_t)hb * EMB;
            const us16* plo = clo + (size_t)hb * EMB;
            float s = 0.f;
            #pragma unroll 8
            for (int jj = lane16; jj < EMB; jj += 16) {
                us16 uh = __ldcg(&phi[jj]), ul = __ldcg(&plo[jj]);
                s += (__half2float(*(__half*)&uh) + __half2float(*(__half*)&ul)) * hw[jj];
            }
            s += __shfl_down_sync(shm, s, 8, 16);
            s += __shfl_down_sync(shm, s, 4, 16);
            s += __shfl_down_sync(shm, s, 2, 16);
            s += __shfl_down_sync(shm, s, 1, 16);
            if (lane16 == 0)
                out[(size_t)hb * T * NCLS + (size_t)(t - 1) * NCLS + hk] = s + head_b[hk];
        }

        // refresh the quasi-static h@w_lo correction every 4th step
        if ((t & 3) == 0)
            mma_pass<true >(smb, chi, clo, B0, acc, cwl,
                            a_base, arx, ahi, b4_off, b2_off, tid);
        else
            mma_pass<false>(smb, chi, clo, B0, acc, cwl,
                            a_base, arx, ahi, b4_off, b2_off, tid);

        float mx = 0.f;
        u32 packh[2], packl[2];
        #pragma unroll
        for (int q = 0; q < 4; q++) {
            float r = sigm(gir[q] + acc[0][q] + cwl[0][q]);
            float z = sigm(giz[q] + acc[1][q] + cwl[1][q]);
            float n = tanhf(gin[q] + r * (acc[2][q] + cwl[2][q] + bhn[q]));
            float hnew = (1.f - z) * n + z * hprev[q];
            mx = fmaxf(mx, fabsf(hnew - hprev[q]));
            hprev[q] = hnew;
            __half hh = __float2half_rn(hnew);
            __half hl = __float2half_rn(hnew - __half2float(hh));
            int half = q >> 1, slot = q & 1;
            ((us16*)&packh[half])[slot] = *(us16*)&hh;
            ((us16*)&packl[half])[slot] = *(us16*)&hl;
        }
        size_t o0 = (size_t)r0 * EMB + j0, o1 = (size_t)(r0 + 8) * EMB + j0;
        __stcg((u32*)(nhi + o0), packh[0]);
        __stcg((u32*)(nhi + o1), packh[1]);
        __stcg((u32*)(nlo + o0), packl[0]);
        __stcg((u32*)(nlo + o1), packl[1]);

        // per-warp max |dh| -> shared atomic -> one global RED (R12 proven path)
        int wmax = __reduce_max_sync(0xFFFFFFFFu, __float_as_int(mx));
        if (lane == 0) atomicMax(&s_mx, wmax);
        __syncthreads();
        if (tid == 0) atomicMax(&g_md4[bt][t], s_mx);

        groupbar(bt);   // h_{t+1} + conv flag visible within group

        bool conv = (__int_as_float(((volatile int*)g_md4[bt])[t]) < CONV_EPS);

        if (conv || t == T - 1) {
            // tail head for step t (+ fixed-point broadcast if converged)
            if (group16 < 12) {
                const us16* phi = nhi + (size_t)hb * EMB;
                const us16* plo = nlo + (size_t)hb * EMB;
                float s = 0.f;
                #pragma unroll 8
                for (int jj = lane16; jj < EMB; jj += 16) {
                    us16 uh = __ldcg(&phi[jj]), ul = __ldcg(&plo[jj]);
                    s += (__half2float(*(__half*)&uh) + __half2float(*(__half*)&ul)) * hw[jj];
                }
                s += __shfl_down_sync(shm, s, 8, 16);
                s += __shfl_down_sync(shm, s, 4, 16);
                s += __shfl_down_sync(shm, s, 2, 16);
                s += __shfl_down_sync(shm, s, 1, 16);
                if (lane16 == 0) {
                    float val = s + head_b[hk];
                    size_t base = (size_t)hb * T * NCLS + (size_t)hk;
                    out[base + (size_t)t * NCLS] = val;
                    for (int tt = t + 1; tt < T; tt++)
                        out[base + (size_t)tt * NCLS] = val;
                }
            }
            break;
        }
    }
}

extern "C" void kernel_launch(void* const* d_in, const int* in_sizes, int n_in,
                              void* d_out, int out_size)
{
    (void)in_sizes; (void)out_size;
    const float* c      = (const float*)d_in[0];
    const float* fc_w   = (const float*)d_in[1];
    const float* fc_b   = (const float*)d_in[2];
    const float* w_ih   = (const float*)d_in[3];
    const float* b_ih   = (const float*)d_in[4];
    const float* w_hh   = (const float*)d_in[5];
    const float* b_hh   = (const float*)d_in[6];
    const float* head_w = (const float*)d_in[7];
    const float* head_b = (const float*)d_in[8];
    const int*   maxT   = (n_in > 9) ? (const int*)d_in[9] : nullptr;

    cudaFuncSetAttribute(gru_mma_kernel,
                         cudaFuncAttributeMaxDynamicSharedMemorySize, SMEM_BYTES);
    gru_mma_kernel<<<NCTA, NTHR, SMEM_BYTES>>>(c, fc_w, fc_b, w_ih, b_ih, w_hh, b_hh,
                                               head_w, head_b, maxT, (float*)d_out);
}

// round 17
// speedup vs baseline: 2.1574x; 1.0402x over previous
#include <cuda_runtime.h>
#include <cuda_fp16.h>

#define EMB   512
#define BATCH 256
#define NCLS  6
#define NCTA  128
#define NGRP  32          // CTAs per independent b-group
#define NTHR  256
#define TMAX  512
#define CONV_EPS 1.5e-3f

#define BPITCH 1040   // bytes/row of w in smem (padded)
#define WS_PL  49920  // one w plane: 48 * 1040
#define HS_OFF 99840
#define HS_PL  32768  // one h plane chunk (256 k): 64 rows * 512B, XOR-swizzled
#define HS_BUF 65536  // 2 planes
#define SMEM_BYTES (HS_OFF + 2 * HS_BUF)   // 230912

typedef unsigned int u32;
typedef unsigned long long u64;
typedef unsigned short us16;

// ---- persistent device state ----
__device__ us16 g_xp[2][BATCH * EMB];        // x fp16 hi/lo planes
__device__ us16 g_hp[2][2][BATCH * EMB];     // h[step parity][plane]
__device__ int  g_md4[4][TMAX];
// prelude barrier (sense-reversing across replays)
__device__ unsigned g_cnt4[4 * 32];
__device__ volatile unsigned g_gen4[4 * 32];
// recurrent-loop barrier: gen encodes ((t+1)<<1)|conv, reset each launch
__device__ unsigned g_cntr[4 * 32];
__device__ volatile unsigned g_genr[4 * 32];

__device__ __forceinline__ u32 smem_u32(const void* p) {
    u32 a; asm("{ .reg .u64 t; cvta.to.shared.u64 t, %1; cvt.u32.u64 %0, t; }" : "=r"(a) : "l"(p));
    return a;
}
__device__ __forceinline__ void cp16(u32 dst, const void* src) {
    u64 g = (u64)__cvta_generic_to_global(src);
    asm volatile("cp.async.cg.shared.global [%0], [%1], 16;" :: "r"(dst), "l"(g));
}
__device__ __forceinline__ void ldsm_x4(u32& r0, u32& r1, u32& r2, u32& r3, u32 addr) {
    asm volatile("ldmatrix.sync.aligned.m8n8.x4.shared.b16 {%0,%1,%2,%3}, [%4];"
                 : "=r"(r0), "=r"(r1), "=r"(r2), "=r"(r3) : "r"(addr));
}
__device__ __forceinline__ void ldsm_x2(u32& r0, u32& r1, u32 addr) {
    asm volatile("ldmatrix.sync.aligned.m8n8.x2.shared.b16 {%0,%1}, [%2];"
                 : "=r"(r0), "=r"(r1) : "r"(addr));
}
__device__ __forceinline__ void mma16816(float* d, u32 a0, u32 a1, u32 a2, u32 a3,
                                         u32 b0, u32 b1) {
    asm volatile("mma.sync.aligned.m16n8k16.row.col.f32.f16.f16.f32 "
                 "{%0,%1,%2,%3}, {%4,%5,%6,%7}, {%8,%9}, {%0,%1,%2,%3};"
                 : "+f"(d[0]), "+f"(d[1]), "+f"(d[2]), "+f"(d[3])
                 : "r"(a0), "r"(a1), "r"(a2), "r"(a3), "r"(b0), "r"(b1));
}
__device__ __forceinline__ float sigm(float v) { return 1.f / (1.f + __expf(-v)); }

// ---- prelude barrier (proven sense-reversing version) ----
__device__ __forceinline__ void groupbar(int bt) {
    __syncthreads();
    __threadfence();
    if (threadIdx.x == 0) {
        unsigned* cnt = &g_cnt4[bt * 32];
        volatile unsigned* gen = &g_gen4[bt * 32];
        unsigned my = *gen;
        unsigned a = atomicAdd(cnt, 1u);
        if (a == NGRP - 1u) {
            *cnt = 0;
            __threadfence();
            *gen = my + 1u;
        } else {
            while (*gen == my) { }
        }
    }
    __syncthreads();
    __threadfence();
}

// ---- stage one 256-k chunk (both fp16 planes, 64 rows) via cp.async ----
__device__ __forceinline__ void stage_chunk(u32 dst, const us16* hi, const us16* lo,
                                            int B0, int kc, int tid) {
    #pragma unroll
    for (int i = 0; i < 16; i++) {
        int idx = tid + i * NTHR;          // 0..4095
        int pl  = idx >> 11;
        int rem = idx & 2047;
        int row = rem >> 5;                // 0..63
        int u   = rem & 31;                // 16B unit along k
        const us16* src = (pl ? lo : hi) + (size_t)(B0 + row) * EMB + kc + u * 8;
        cp16(dst + pl * HS_PL + row * 512 + ((u ^ (row & 7)) << 4), src);
    }
    asm volatile("cp.async.commit_group;" ::: "memory");
}

// ---- full K=512 pass ----
// acc[3][4]  = h_hi@w_hi + h_lo@w_hi   (every step)
// cwl[3][4]  = h_hi@w_lo               (recomputed only when REFRESH)
// Caller pre-stages chunk0 into buf0.
template<bool REFRESH>
__device__ __forceinline__ void mma_pass(u32 smb, const us16* hi, const us16* lo, int B0,
                                         float acc[3][4], float cwl[3][4],
                                         u32 a_base, u32 arx, u32 ahi,
                                         u32 b4_off, u32 b2_off, int tid) {
    #pragma unroll
    for (int g = 0; g < 3; g++)
        #pragma unroll
        for (int q = 0; q < 4; q++) {
            acc[g][q] = 0.f;
            if (REFRESH) cwl[g][q] = 0.f;
        }

    #pragma unroll
    for (int c = 0; c < 2; c++) {
        if (c == 0) {
            stage_chunk(smb + HS_OFF + HS_BUF, hi, lo, B0, 256, tid);
            asm volatile("cp.async.wait_group 1;" ::: "memory");
        } else {
            asm volatile("cp.async.wait_group 0;" ::: "memory");
        }
        __syncthreads();

        u32 ab = smb + HS_OFF + c * HS_BUF + a_base;
        #pragma unroll
        for (int kk = 0; kk < 16; kk++) {
            u32 au = (u32)(((kk * 2 + ahi) ^ arx) << 4);
            u32 kb = (u32)(c * 512 + kk * 32);
            u32 ah0, ah1, ah2, ah3, al0, al1, al2, al3;
            u32 bh0, bh1, bh2, bh3, bg0, bg1;
            ldsm_x4(ah0, ah1, ah2, ah3, ab + au);
            ldsm_x4(al0, al1, al2, al3, ab + HS_PL + au);
            ldsm_x4(bh0, bh1, bh2, bh3, smb + b4_off + kb);
            ldsm_x2(bg0, bg1,           smb + b2_off + kb);
            // main + h_lo correction (every step)
            mma16816(acc[0], ah0, ah1, ah2, ah3, bh0, bh1);
            mma16816(acc[1], ah0, ah1, ah2, ah3, bh2, bh3);
            mma16816(acc[2], ah0, ah1, ah2, ah3, bg0, bg1);
            mma16816(acc[0], al0, al1, al2, al3, bh0, bh1);
            mma16816(acc[1], al0, al1, al2, al3, bh2, bh3);
            mma16816(acc[2], al0, al1, al2, al3, bg0, bg1);
            if (REFRESH) {
                u32 cl0, cl1, cl2, cl3, cg0, cg1;
                ldsm_x4(cl0, cl1, cl2, cl3, smb + WS_PL + b4_off + kb);
                ldsm_x2(cg0, cg1,           smb + WS_PL + b2_off + kb);
                mma16816(cwl[0], ah0, ah1, ah2, ah3, cl0, cl1);
                mma16816(cwl[1], ah0, ah1, ah2, ah3, cl2, cl3);
                mma16816(cwl[2], ah0, ah1, ah2, ah3, cg0, cg1);
            }
        }
    }
}

// ---- load a 48-row weight slice into fp16 hi/lo smem planes (padded pitch) ----
__device__ __forceinline__ void load_ws(char* smraw, const float* wsrc, int J0, int tid) {
    us16* whi = (us16*)smraw;
    us16* wlo = (us16*)(smraw + WS_PL);
    for (int e = tid; e < 48 * EMB; e += NTHR) {
        int n = e >> 9, k = e & 511;
        int g = n >> 4, jj = n & 15;
        float w = wsrc[((size_t)(g * EMB + J0 + jj)) * EMB + k];
        __half h = __float2half_rn(w);
        __half l = __float2half_rn(w - __half2float(h));
        whi[n * (BPITCH / 2) + k] = *(us16*)&h;
        wlo[n * (BPITCH / 2) + k] = *(us16*)&l;
    }
}

__global__ void __launch_bounds__(NTHR, 1)
gru_mma_kernel(const float* __restrict__ c,     const float* __restrict__ fc_w,
               const float* __restrict__ fc_b,  const float* __restrict__ w_ih,
               const float* __restrict__ b_ih,  const float* __restrict__ w_hh,
               const float* __restrict__ b_hh,  const float* __restrict__ head_w,
               const float* __restrict__ head_b,const int*   __restrict__ maxT,
               float* __restrict__ out)
{
    extern __shared__ char smraw[];
    const u32 smb = smem_u32(smraw);
    __shared__ int s_mx;
    __shared__ int s_cv;

    const int tid = threadIdx.x;
    const int cta = blockIdx.x;
    const int wid = tid >> 5, lane = tid & 31;

    int T = (maxT != nullptr) ? maxT[0] : TMAX;
    if (T < 1 || T > TMAX) T = TMAX;

    const int bt = cta >> 5;                 // b-group 0..3 (independent)
    const int jt = cta & 31;                 // j-tile within group
    const int B0 = bt * 64;
    const int J0 = jt * 16;
    const int lg = jt * NTHR + tid;          // 0..8191 within group
    const int mtile = wid & 3, p = wid >> 2;

    // A fragment per-lane constants (swizzled layout)
    const int arow = mtile * 16 + (lane & 15);          // 0..63
    const u32 a_base = (u32)(arow * 512);
    const u32 arx    = (u32)(arow & 7);
    const u32 ahi    = (u32)(lane >> 4);                // 0/1

    // B fragment per-lane byte offsets (padded layout)
    const u32 b4_off = (u32)(((lane >> 4) * 16 + p * 8 + (lane & 7)) * BPITCH
                             + ((lane >> 3) & 1) * 16);
    const u32 b2_off = (u32)((32 + p * 8 + (lane & 7)) * BPITCH + ((lane >> 3) & 1) * 16);

    // this thread's 4 output cells: rows r0,r0+8 ; cols j0,j0+1
    const int r0 = B0 + mtile * 16 + (lane >> 2);
    const int j0 = J0 + p * 8 + 2 * (lane & 3);

    const int group16 = tid >> 4, lane16 = tid & 15;
    // head assignment (group-local): 384 dots over 32 CTAs
    const int hp_idx = jt * 12 + group16;               // 0..383 (group16<12)
    const int hb = B0 + hp_idx / NCLS, hk = hp_idx % NCLS;

    // ---------------- Phase A (tiled in smem): x = tanh(c @ fc_w^T + fc_b) --------
    for (int i = lg; i < 64 * EMB; i += NGRP * NTHR) {
        int o = B0 * EMB + i;
        g_hp[0][0][o] = 0; g_hp[0][1][o] = 0;
    }
    for (int i = lg; i < TMAX; i += NGRP * NTHR) ((volatile int*)g_md4[bt])[i] = 0;
    if (lg == 0) { g_cntr[bt * 32] = 0; g_genr[bt * 32] = 0; }   // recurrent barrier reset

    {
        float* wfs = (float*)smraw;                   // 16 rows x 513 floats
        float* cfs = (float*)(smraw + HS_OFF);        // 64 rows x 512 floats

        for (int e = tid; e < 16 * 128; e += NTHR) {
            int r = e >> 7, kq = (e & 127) << 2;
            float4 v = *(const float4*)(fc_w + (size_t)(J0 + r) * EMB + kq);
            float* dst = wfs + r * 513 + kq;
            dst[0] = v.x; dst[1] = v.y; dst[2] = v.z; dst[3] = v.w;
        }
        for (int e = tid; e < 64 * 128; e += NTHR) {
            int r = e >> 7, kq = (e & 127) << 2;
            cp16(smb + HS_OFF + (u32)((r * 512 + kq) << 2),
                 c + (size_t)(B0 + r) * EMB + kq);
        }
        asm volatile("cp.async.commit_group;" ::: "memory");
        asm volatile("cp.async.wait_group 0;" ::: "memory");
        __syncthreads();

        const int il = tid & 15, b4 = (tid >> 4) << 2;
        const float* wrow = wfs + il * 513;
        const float* c0 = cfs + b4 * 512;
        float ax0 = 0.f, ax1 = 0.f, ax2 = 0.f, ax3 = 0.f;
        #pragma unroll 8
        for (int k = 0; k < 512; k++) {
            float wv = wrow[k];
            ax0 += c0[k] * wv;
            ax1 += c0[512 + k] * wv;
            ax2 += c0[1024 + k] * wv;
            ax3 += c0[1536 + k] * wv;
        }
        float bb = fc_b[J0 + il];
        float xs[4] = { tanhf(ax0 + bb), tanhf(ax1 + bb), tanhf(ax2 + bb), tanhf(ax3 + bb) };
        #pragma unroll
        for (int q = 0; q < 4; q++) {
            size_t o = (size_t)(B0 + b4 + q) * EMB + (J0 + il);
            __half xh = __float2half_rn(xs[q]);
            __half xl = __float2half_rn(xs[q] - __half2float(xh));
            g_xp[0][o] = *(us16*)&xh; g_xp[1][o] = *(us16*)&xl;
        }
        __syncthreads();
    }
    groupbar(bt);   // x + barrier resets visible group-wide

    // ---------------- gi pass: ws <- w_ih ; acc+cwl = x @ w_ih^T (3 products) ------
    load_ws(smraw, w_ih, J0, tid);
    __syncthreads();

    float acc[3][4], cwl[3][4];
    stage_chunk(smb + HS_OFF, g_xp[0], g_xp[1], B0, 0, tid);
    mma_pass<true>(smb, g_xp[0], g_xp[1], B0, acc, cwl,
                   a_base, arx, ahi, b4_off, b2_off, tid);

    float gir[4], giz[4], gin[4], bhn[4], hprev[4];
    #pragma unroll
    for (int q = 0; q < 4; q++) {
        int jq = j0 + (q & 1);
        gir[q] = acc[0][q] + cwl[0][q] + b_ih[jq]           + b_hh[jq];
        giz[q] = acc[1][q] + cwl[1][q] + b_ih[EMB + jq]     + b_hh[EMB + jq];
        gin[q] = acc[2][q] + cwl[2][q] + b_ih[2 * EMB + jq];
        bhn[q] = b_hh[2 * EMB + jq];
        hprev[q] = 0.f;
    }
    __syncthreads();

    // ---------------- ws <- w_hh (resident for the whole recurrence) ---------------
    load_ws(smraw, w_hh, J0, tid);
    __syncthreads();

    const float* hw = head_w + (size_t)hk * EMB;
    const unsigned shm = 0xFFFFu << (tid & 16);

    // ---------------- Recurrent loop -----------------------------------------------
    for (int t = 0; t < T; t++) {
        const us16* chi = g_hp[t & 1][0];
        const us16* clo = g_hp[t & 1][1];
        us16* nhi = g_hp[(t + 1) & 1][0];
        us16* nlo = g_hp[(t + 1) & 1][1];

        if (tid == 0) s_mx = 0;
        // kick off chunk 0 of h_t staging, then do the deferred head(t-1) in its shadow
        stage_chunk(smb + HS_OFF, chi, clo, B0, 0, tid);

        if (t > 0 && group16 < 12) {
            const us16* phi = chi + (size_t)hb * EMB;
            const us16* plo = clo + (size_t)hb * EMB;
            float s = 0.f;
            #pragma unroll 8
            for (int jj = lane16; jj < EMB; jj += 16) {
                us16 uh = __ldcg(&phi[jj]), ul = __ldcg(&plo[jj]);
                s += (__half2float(*(__half*)&uh) + __half2float(*(__half*)&ul)) * hw[jj];
            }
            s += __shfl_down_sync(shm, s, 8, 16);
            s += __shfl_down_sync(shm, s, 4, 16);
            s += __shfl_down_sync(shm, s, 2, 16);
            s += __shfl_down_sync(shm, s, 1, 16);
            if (lane16 == 0)
                out[(size_t)hb * T * NCLS + (size_t)(t - 1) * NCLS + hk] = s + head_b[hk];
        }

        // refresh the quasi-static h@w_lo correction every 8th step
        if ((t & 7) == 0)
            mma_pass<true >(smb, chi, clo, B0, acc, cwl,
                            a_base, arx, ahi, b4_off, b2_off, tid);
        else
            mma_pass<false>(smb, chi, clo, B0, acc, cwl,
                            a_base, arx, ahi, b4_off, b2_off, tid);

        float mx = 0.f;
        u32 packh[2], packl[2];
        #pragma unroll
        for (int q = 0; q < 4; q++) {
            float r = sigm(gir[q] + acc[0][q] + cwl[0][q]);
            float z = sigm(giz[q] + acc[1][q] + cwl[1][q]);
            float n = tanhf(gin[q] + r * (acc[2][q] + cwl[2][q] + bhn[q]));
            float hnew = (1.f - z) * n + z * hprev[q];
            mx = fmaxf(mx, fabsf(hnew - hprev[q]));
            hprev[q] = hnew;
            __half hh = __float2half_rn(hnew);
            __half hl = __float2half_rn(hnew - __half2float(hh));
            int half = q >> 1, slot = q & 1;
            ((us16*)&packh[half])[slot] = *(us16*)&hh;
            ((us16*)&packl[half])[slot] = *(us16*)&hl;
        }
        size_t o0 = (size_t)r0 * EMB + j0, o1 = (size_t)(r0 + 8) * EMB + j0;
        __stcg((u32*)(nhi + o0), packh[0]);
        __stcg((u32*)(nhi + o1), packh[1]);
        __stcg((u32*)(nlo + o0), packl[0]);
        __stcg((u32*)(nlo + o1), packl[1]);

        // per-warp max |dh| -> shared atomic -> one global RED (R12 proven path)
        int wmax = __reduce_max_sync(0xFFFFFFFFu, __float_as_int(mx));
        if (lane == 0) atomicMax(&s_mx, wmax);
        __syncthreads();
        if (tid == 0) atomicMax(&g_md4[bt][t], s_mx);

        // ---- barrier with conv fused into the release word ------------------------
        __syncthreads();
        __threadfence();   // orders h stores + g_md4 atomicMax before arrival
        if (tid == 0) {
            unsigned* cnt = &g_cntr[bt * 32];
            volatile unsigned* gen = &g_genr[bt * 32];
            unsigned a = atomicAdd(cnt, 1u);
            if (a == NGRP - 1u) {
                *cnt = 0;
                int gm = atomicMax(&g_md4[bt][t], 0);   // L2-coherent read of final max
                int cv = (__int_as_float(gm) < CONV_EPS) ? 1 : 0;
                __threadfence();
                *gen = (unsigned)(((t + 1) << 1) | cv);
                s_cv = cv;
            } else {
                unsigned gw;
                while ((int)((gw = *gen) >> 1) <= t) { }
                s_cv = (int)(gw & 1u);
            }
        }
        __syncthreads();
        __threadfence();   // acquire: h_{t+1} from all CTAs now readable
        const bool conv = (s_cv != 0);

        if (conv || t == T - 1) {
            // tail head for step t (+ fixed-point broadcast if converged)
            if (group16 < 12) {
                const us16* phi = nhi + (size_t)hb * EMB;
                const us16* plo = nlo + (size_t)hb * EMB;
                float s = 0.f;
                #pragma unroll 8
                for (int jj = lane16; jj < EMB; jj += 16) {
                    us16 uh = __ldcg(&phi[jj]), ul = __ldcg(&plo[jj]);
                    s += (__half2float(*(__half*)&uh) + __half2float(*(__half*)&ul)) * hw[jj];
                }
                s += __shfl_down_sync(shm, s, 8, 16);
                s += __shfl_down_sync(shm, s, 4, 16);
                s += __shfl_down_sync(shm, s, 2, 16);
                s += __shfl_down_sync(shm, s, 1, 16);
                if (lane16 == 0) {
                    float val = s + head_b[hk];
                    size_t base = (size_t)hb * T * NCLS + (size_t)hk;
                    out[base + (size_t)t * NCLS] = val;
                    for (int tt = t + 1; tt < T; tt++)
                        out[base + (size_t)tt * NCLS] = val;
                }
            }
            break;
        }
    }
}

extern "C" void kernel_launch(void* const* d_in, const int* in_sizes, int n_in,
                              void* d_out, int out_size)
{
    (void)in_sizes; (void)out_size;
    const float* c      = (const float*)d_in[0];
    const float* fc_w   = (const float*)d_in[1];
    const float* fc_b   = (const float*)d_in[2];
    const float* w_ih   = (const float*)d_in[3];
    const float* b_ih   = (const float*)d_in[4];
    const float* w_hh   = (const float*)d_in[5];
    const float* b_hh   = (const float*)d_in[6];
    const float* head_w = (const float*)d_in[7];
    const float* head_b = (const float*)d_in[8];
    const int*   maxT   = (n_in > 9) ? (const int*)d_in[9] : nullptr;

    cudaFuncSetAttribute(gru_mma_kernel,
                         cudaFuncAttributeMaxDynamicSharedMemorySize, SMEM_BYTES);
    gru_mma_kernel<<<NCTA, NTHR, SMEM_BYTES>>>(c, fc_w, fc_b, w_ih, b_ih, w_hh, b_hh,
                                               head_w, head_b, maxT, (float*)d_out);
}